// round 1
// baseline (speedup 1.0000x reference)
#include <cuda_runtime.h>
#include <math.h>

#define N_NODES 50000
#define N_EDGES 800000
#define F 128
#define NCLS 16

// ---------------- device scratch (static allocs are allowed) ----------------
__device__ float g_bufA[N_NODES * F];   // 25.6 MB
__device__ float g_bufB[N_NODES * F];   // 25.6 MB
__device__ float g_dinv[N_NODES];
__device__ int   g_cnt[N_NODES];
__device__ int   g_cur[N_NODES];
__device__ int   g_rowstart[N_NODES + 1];
__device__ int   g_bsums[64];
__device__ int   g_csr[N_EDGES];

// ---------------- CSR construction ----------------
__global__ void k_init(int n) {
    int i = blockIdx.x * blockDim.x + threadIdx.x;
    if (i < n) { g_cnt[i] = 0; g_cur[i] = 0; }
}

__global__ void k_count(const int* __restrict__ ei, int e) {
    int i = blockIdx.x * blockDim.x + threadIdx.x;
    if (i < e) atomicAdd(&g_cnt[ei[N_EDGES + i]], 1);
}

__global__ void k_dinv(int n) {
    int i = blockIdx.x * blockDim.x + threadIdx.x;
    if (i < n) g_dinv[i] = rsqrtf((float)(g_cnt[i] + 1));  // +1 self-loop
}

__global__ void k_scan1(int n) {
    __shared__ int wsum[32];
    int t = threadIdx.x;
    int gid = blockIdx.x * 1024 + t;
    int lane = t & 31, w = t >> 5;
    int v = (gid < n) ? g_cnt[gid] : 0;
    int x = v;
#pragma unroll
    for (int o = 1; o < 32; o <<= 1) {
        int y = __shfl_up_sync(0xffffffffu, x, o);
        if (lane >= o) x += y;
    }
    if (lane == 31) wsum[w] = x;
    __syncthreads();
    if (w == 0) {
        int s = wsum[t];
        int xs = s;
#pragma unroll
        for (int o = 1; o < 32; o <<= 1) {
            int y = __shfl_up_sync(0xffffffffu, xs, o);
            if (lane >= o) xs += y;
        }
        wsum[t] = xs - s;  // exclusive
        if (t == 31) g_bsums[blockIdx.x] = xs;  // block total
    }
    __syncthreads();
    if (gid < n) g_rowstart[gid] = x - v + wsum[w];
}

__global__ void k_scan2(int nb, int n) {
    if (blockIdx.x == 0 && threadIdx.x == 0) {
        int run = 0;
        for (int i = 0; i < nb; i++) { int v = g_bsums[i]; g_bsums[i] = run; run += v; }
        g_rowstart[n] = run;
    }
}

__global__ void k_scan3(int n) {
    int gid = blockIdx.x * 1024 + threadIdx.x;
    if (gid < n) g_rowstart[gid] += g_bsums[blockIdx.x];
}

__global__ void k_fill(const int* __restrict__ ei, int e) {
    int i = blockIdx.x * blockDim.x + threadIdx.x;
    if (i < e) {
        int d = ei[N_EDGES + i];
        int p = atomicAdd(&g_cur[d], 1);
        g_csr[g_rowstart[d] + p] = ei[i];
    }
}

// ---------------- SpMM: Z = Â H  (warp per row, float4 per lane) ----------------
__global__ __launch_bounds__(256) void k_spmm(const float* __restrict__ H,
                                              float* __restrict__ Z) {
    int warp = (blockIdx.x * blockDim.x + threadIdx.x) >> 5;
    if (warp >= N_NODES) return;
    int lane = threadIdx.x & 31;
    const float4* H4 = (const float4*)H;
    float di = g_dinv[warp];
    float4 h = H4[warp * 32 + lane];
    float4 acc;
    acc.x = di * h.x; acc.y = di * h.y; acc.z = di * h.z; acc.w = di * h.w;
    int beg = g_rowstart[warp], end = g_rowstart[warp + 1];
    int j = beg;
    for (; j + 1 < end; j += 2) {
        int s0 = g_csr[j], s1 = g_csr[j + 1];
        float w0 = g_dinv[s0], w1 = g_dinv[s1];
        float4 v0 = H4[s0 * 32 + lane];
        float4 v1 = H4[s1 * 32 + lane];
        acc.x += w0 * v0.x + w1 * v1.x;
        acc.y += w0 * v0.y + w1 * v1.y;
        acc.z += w0 * v0.z + w1 * v1.z;
        acc.w += w0 * v0.w + w1 * v1.w;
    }
    if (j < end) {
        int s0 = g_csr[j];
        float w0 = g_dinv[s0];
        float4 v0 = H4[s0 * 32 + lane];
        acc.x += w0 * v0.x; acc.y += w0 * v0.y;
        acc.z += w0 * v0.z; acc.w += w0 * v0.w;
    }
    acc.x *= di; acc.y *= di; acc.z *= di; acc.w *= di;
    ((float4*)Z)[warp * 32 + lane] = acc;
}

// ---------------- GEMM 128-out: C = relu(A*W + b), A[M,128], W[128,128] ----------------
__global__ __launch_bounds__(256, 2) void k_gemm128(const float* __restrict__ A,
                                                    const float* __restrict__ W,
                                                    const float* __restrict__ bias,
                                                    float* __restrict__ C, int M) {
    __shared__ float As[128][9];   // [row][kk], pad 9 to break conflicts
    __shared__ float Ws[8][128];   // [kk][col]
    int t = threadIdx.x;
    int tx = t & 15, ty = t >> 4;
    int rowBase = blockIdx.x * 128;

    float acc[8][8];
#pragma unroll
    for (int i = 0; i < 8; i++)
#pragma unroll
        for (int j = 0; j < 8; j++) acc[i][j] = 0.f;

    int ar = t >> 1;
    int ac = (t & 1) * 4;
    int wk = t >> 5;
    int wc = (t & 31) * 4;

    for (int k0 = 0; k0 < 128; k0 += 8) {
        // A chunk: 128 rows x 8 k
        int grow = rowBase + ar;
        float4 av = (grow < M) ? *(const float4*)&A[grow * 128 + k0 + ac]
                               : make_float4(0.f, 0.f, 0.f, 0.f);
        As[ar][ac + 0] = av.x; As[ar][ac + 1] = av.y;
        As[ar][ac + 2] = av.z; As[ar][ac + 3] = av.w;
        // W chunk: 8 k x 128 cols
        float4 wv = *(const float4*)&W[(k0 + wk) * 128 + wc];
        *(float4*)&Ws[wk][wc] = wv;
        __syncthreads();
#pragma unroll
        for (int kk = 0; kk < 8; kk++) {
            float a[8], b[8];
#pragma unroll
            for (int i = 0; i < 8; i++) a[i] = As[ty + 16 * i][kk];
#pragma unroll
            for (int j = 0; j < 8; j++) b[j] = Ws[kk][tx + 16 * j];
#pragma unroll
            for (int i = 0; i < 8; i++)
#pragma unroll
                for (int j = 0; j < 8; j++) acc[i][j] += a[i] * b[j];
        }
        __syncthreads();
    }

    float bcol[8];
#pragma unroll
    for (int j = 0; j < 8; j++) bcol[j] = __ldg(&bias[tx + 16 * j]);
#pragma unroll
    for (int i = 0; i < 8; i++) {
        int row = rowBase + ty + 16 * i;
        if (row < M) {
#pragma unroll
            for (int j = 0; j < 8; j++) {
                float v = acc[i][j] + bcol[j];
                C[row * 128 + tx + 16 * j] = fmaxf(v, 0.f);
            }
        }
    }
}

// ---------------- head: out = log_softmax(Y*Wf3 + bf3), 16 classes ----------------
__global__ __launch_bounds__(256) void k_final(const float* __restrict__ Y,
                                               const float* __restrict__ Wf,
                                               const float* __restrict__ bf,
                                               float* __restrict__ out, int M) {
    __shared__ float Ws[128][16];   // [k][c]
    __shared__ float Ys[16][132];   // [r][k], pad 132 (16B-aligned rows, no conflicts)
    int t = threadIdx.x;
    int rowBase = blockIdx.x * 16;

    // load Wf3: 2048 floats = 512 float4
    for (int i = t; i < 512; i += 256) {
        float4 v = ((const float4*)Wf)[i];
        int k = i >> 2, c = (i & 3) * 4;
        *(float4*)&Ws[k][c] = v;
    }
    // load 16 rows of Y: 2048 floats
    for (int i = t; i < 512; i += 256) {
        int r = i >> 5, c4 = (i & 31) * 4;
        int grow = rowBase + r;
        float4 v = (grow < M) ? ((const float4*)Y)[grow * 32 + (i & 31)]
                              : make_float4(0.f, 0.f, 0.f, 0.f);
        Ys[r][c4 + 0] = v.x; Ys[r][c4 + 1] = v.y;
        Ys[r][c4 + 2] = v.z; Ys[r][c4 + 3] = v.w;
    }
    __syncthreads();

    int r = t >> 4, c = t & 15;
    float acc = __ldg(&bf[c]);
#pragma unroll
    for (int k = 0; k < 128; k++) acc += Ys[r][k] * Ws[k][c];

    // log_softmax over 16-lane group
    float m = acc;
#pragma unroll
    for (int o = 8; o > 0; o >>= 1) m = fmaxf(m, __shfl_xor_sync(0xffffffffu, m, o));
    float e = expf(acc - m);
    float s = e;
#pragma unroll
    for (int o = 8; o > 0; o >>= 1) s += __shfl_xor_sync(0xffffffffu, s, o);
    float res = acc - m - logf(s);

    int grow = rowBase + r;
    if (grow < M) out[grow * 16 + c] = res;
}

// ---------------- launch ----------------
extern "C" void kernel_launch(void* const* d_in, const int* in_sizes, int n_in,
                              void* d_out, int out_size) {
    const float* x   = (const float*)d_in[0];
    const int*   ei  = (const int*)d_in[1];
    // d_in[2] = TRAIN (ignored)
    const float* W1  = (const float*)d_in[3];
    const float* b1  = (const float*)d_in[4];
    const float* W2  = (const float*)d_in[5];
    const float* b2  = (const float*)d_in[6];
    const float* W3  = (const float*)d_in[7];
    const float* b3  = (const float*)d_in[8];
    const float* Wf1 = (const float*)d_in[9];
    const float* bf1 = (const float*)d_in[10];
    const float* Wf2 = (const float*)d_in[11];
    const float* bf2 = (const float*)d_in[12];
    const float* Wf3 = (const float*)d_in[13];
    const float* bf3 = (const float*)d_in[14];
    float* out = (float*)d_out;

    const int N = N_NODES;
    const int E = N_EDGES;

    float* bufA; float* bufB;
    cudaGetSymbolAddress((void**)&bufA, g_bufA);
    cudaGetSymbolAddress((void**)&bufB, g_bufB);

    const int NB_SCAN = (N + 1023) / 1024;  // 49

    // CSR build
    k_init<<<(N + 255) / 256, 256>>>(N);
    k_count<<<(E + 255) / 256, 256>>>(ei, E);
    k_dinv<<<(N + 255) / 256, 256>>>(N);
    k_scan1<<<NB_SCAN, 1024>>>(N);
    k_scan2<<<1, 32>>>(NB_SCAN, N);
    k_scan3<<<NB_SCAN, 1024>>>(N);
    k_fill<<<(E + 255) / 256, 256>>>(ei, E);

    const int spmmBlocks = (N * 32 + 255) / 256;
    const int gemmBlocks = (N + 127) / 128;

    // layer 1: Z = Â x ; Y = relu(Z W1 + b1)
    k_spmm<<<spmmBlocks, 256>>>(x, bufA);
    k_gemm128<<<gemmBlocks, 256>>>(bufA, W1, b1, bufB, N);
    // layer 2
    k_spmm<<<spmmBlocks, 256>>>(bufB, bufA);
    k_gemm128<<<gemmBlocks, 256>>>(bufA, W2, b2, bufB, N);
    // layer 3
    k_spmm<<<spmmBlocks, 256>>>(bufB, bufA);
    k_gemm128<<<gemmBlocks, 256>>>(bufA, W3, b3, bufB, N);
    // MLP head
    k_gemm128<<<gemmBlocks, 256>>>(bufB, Wf1, bf1, bufA, N);
    k_gemm128<<<gemmBlocks, 256>>>(bufA, Wf2, bf2, bufB, N);
    k_final<<<(N + 15) / 16, 256>>>(bufB, Wf3, bf3, out, N);
}

// round 3
// speedup vs baseline: 1.1311x; 1.1311x over previous
#include <cuda_runtime.h>
#include <cuda_bf16.h>
#include <math.h>
#include <cstdint>

#define N_NODES 50000
#define N_EDGES 800000
#define F 128
#define NCLS 16

// ---------------- device scratch ----------------
__device__ float g_bufA[N_NODES * F];
__device__ float g_bufB[N_NODES * F];
__device__ float g_dinv[N_NODES];
__device__ int   g_cnt[N_NODES];
__device__ int   g_cur[N_NODES];
__device__ int   g_rowstart[N_NODES + 1];
__device__ int   g_bsums[64];
__device__ int   g_csr[N_EDGES];
// 5 weight images, each: hi[16384] bf16 then lo[16384] bf16, [k][n] row-major.
__device__ __align__(16) __nv_bfloat16 g_Wimg[5 * 2 * 16384];

// ---------------- CSR construction ----------------
__global__ void k_init(int n) {
    int i = blockIdx.x * blockDim.x + threadIdx.x;
    if (i < n) { g_cnt[i] = 0; g_cur[i] = 0; }
}
__global__ void k_count(const int* __restrict__ ei, int e) {
    int i = blockIdx.x * blockDim.x + threadIdx.x;
    if (i < e) atomicAdd(&g_cnt[ei[N_EDGES + i]], 1);
}
__global__ void k_dinv(int n) {
    int i = blockIdx.x * blockDim.x + threadIdx.x;
    if (i < n) g_dinv[i] = rsqrtf((float)(g_cnt[i] + 1));
}
__global__ void k_scan1(int n) {
    __shared__ int wsum[32];
    int t = threadIdx.x;
    int gid = blockIdx.x * 1024 + t;
    int lane = t & 31, w = t >> 5;
    int v = (gid < n) ? g_cnt[gid] : 0;
    int x = v;
#pragma unroll
    for (int o = 1; o < 32; o <<= 1) {
        int y = __shfl_up_sync(0xffffffffu, x, o);
        if (lane >= o) x += y;
    }
    if (lane == 31) wsum[w] = x;
    __syncthreads();
    if (w == 0) {
        int s = wsum[t];
        int xs = s;
#pragma unroll
        for (int o = 1; o < 32; o <<= 1) {
            int y = __shfl_up_sync(0xffffffffu, xs, o);
            if (lane >= o) xs += y;
        }
        wsum[t] = xs - s;
        if (t == 31) g_bsums[blockIdx.x] = xs;
    }
    __syncthreads();
    if (gid < n) g_rowstart[gid] = x - v + wsum[w];
}
__global__ void k_scan2(int nb, int n) {
    if (blockIdx.x == 0 && threadIdx.x == 0) {
        int run = 0;
        for (int i = 0; i < nb; i++) { int v = g_bsums[i]; g_bsums[i] = run; run += v; }
        g_rowstart[n] = run;
    }
}
__global__ void k_scan3(int n) {
    int gid = blockIdx.x * 1024 + threadIdx.x;
    if (gid < n) g_rowstart[gid] += g_bsums[blockIdx.x];
}
__global__ void k_fill(const int* __restrict__ ei, int e) {
    int i = blockIdx.x * blockDim.x + threadIdx.x;
    if (i < e) {
        int d = ei[N_EDGES + i];
        int p = atomicAdd(&g_cur[d], 1);
        g_csr[g_rowstart[d] + p] = ei[i];
    }
}

// ---------------- weight split: W fp32 [k][n] -> hi/lo bf16 [k][n] ----------------
__global__ void k_wconv(const float* __restrict__ W0, const float* __restrict__ W1,
                        const float* __restrict__ W2, const float* __restrict__ W3,
                        const float* __restrict__ W4) {
    const float* Ws[5] = {W0, W1, W2, W3, W4};
    int b = blockIdx.x;
    const float* W = Ws[b];
    __nv_bfloat16* hi = &g_Wimg[b * 2 * 16384];
    __nv_bfloat16* lo = hi + 16384;
    for (int idx = threadIdx.x; idx < 16384; idx += blockDim.x) {
        float v = W[idx];
        __nv_bfloat16 h = __float2bfloat16(v);
        __nv_bfloat16 l = __float2bfloat16(v - __bfloat162float(h));
        hi[idx] = h;
        lo[idx] = l;
    }
}

// ---------------- SpMM: Z = Â H ----------------
__global__ __launch_bounds__(256) void k_spmm(const float* __restrict__ H,
                                              float* __restrict__ Z) {
    int warp = (blockIdx.x * blockDim.x + threadIdx.x) >> 5;
    if (warp >= N_NODES) return;
    int lane = threadIdx.x & 31;
    const float4* H4 = (const float4*)H;
    float di = g_dinv[warp];
    float4 h = H4[warp * 32 + lane];
    float4 acc;
    acc.x = di * h.x; acc.y = di * h.y; acc.z = di * h.z; acc.w = di * h.w;
    int beg = g_rowstart[warp], end = g_rowstart[warp + 1];
    int j = beg;
    for (; j + 1 < end; j += 2) {
        int s0 = g_csr[j], s1 = g_csr[j + 1];
        float w0 = g_dinv[s0], w1 = g_dinv[s1];
        float4 v0 = H4[s0 * 32 + lane];
        float4 v1 = H4[s1 * 32 + lane];
        acc.x += w0 * v0.x + w1 * v1.x;
        acc.y += w0 * v0.y + w1 * v1.y;
        acc.z += w0 * v0.z + w1 * v1.z;
        acc.w += w0 * v0.w + w1 * v1.w;
    }
    if (j < end) {
        int s0 = g_csr[j];
        float w0 = g_dinv[s0];
        float4 v0 = H4[s0 * 32 + lane];
        acc.x += w0 * v0.x; acc.y += w0 * v0.y;
        acc.z += w0 * v0.z; acc.w += w0 * v0.w;
    }
    acc.x *= di; acc.y *= di; acc.z *= di; acc.w *= di;
    ((float4*)Z)[warp * 32 + lane] = acc;
}

// ---------------- mma.sync helpers ----------------
__device__ __forceinline__ void ldsm_x4(uint32_t* r, uint32_t addr) {
    asm volatile("ldmatrix.sync.aligned.m8n8.x4.shared.b16 {%0,%1,%2,%3}, [%4];"
                 : "=r"(r[0]), "=r"(r[1]), "=r"(r[2]), "=r"(r[3]) : "r"(addr));
}
__device__ __forceinline__ void ldsm_x4t(uint32_t* r, uint32_t addr) {
    asm volatile("ldmatrix.sync.aligned.m8n8.x4.trans.shared.b16 {%0,%1,%2,%3}, [%4];"
                 : "=r"(r[0]), "=r"(r[1]), "=r"(r[2]), "=r"(r[3]) : "r"(addr));
}
__device__ __forceinline__ void mma16816(float* d, const uint32_t* a, const uint32_t* b) {
    asm volatile(
        "mma.sync.aligned.m16n8k16.row.col.f32.bf16.bf16.f32 "
        "{%0,%1,%2,%3}, {%4,%5,%6,%7}, {%8,%9}, {%0,%1,%2,%3};"
        : "+f"(d[0]), "+f"(d[1]), "+f"(d[2]), "+f"(d[3])
        : "r"(a[0]), "r"(a[1]), "r"(a[2]), "r"(a[3]), "r"(b[0]), "r"(b[1]));
}
__device__ __forceinline__ uint32_t smem_u32(const void* p) {
    uint32_t a;
    asm("{ .reg .u64 t; cvta.to.shared.u64 t, %1; cvt.u32.u64 %0, t; }" : "=r"(a) : "l"(p));
    return a;
}

// ---------------- tensor GEMM: C = relu(A*W + b), bf16 hi/lo split ----------------
#define PITCH 136                       // bf16 elements per smem row (272 B)
#define TILE_BYTES (128 * PITCH * 2)    // 34816
#define SM_BIAS 0
#define SM_AHI  1024
#define SM_ALO  (SM_AHI + TILE_BYTES)
#define SM_WHI  (SM_ALO + TILE_BYTES)
#define SM_WLO  (SM_WHI + TILE_BYTES)
#define SM_TOTAL (SM_WLO + TILE_BYTES)  // 140288

__global__ __launch_bounds__(256, 1) void k_gemm_tc(const float* __restrict__ A,
                                                    const uint4* __restrict__ Bimg,
                                                    const float* __restrict__ bias,
                                                    float* __restrict__ C, int M) {
    extern __shared__ char smem[];
    uint32_t sb = smem_u32(smem);
    int tid = threadIdx.x;
    int wid = tid >> 5, lane = tid & 31;
    int rowBase = blockIdx.x * 128;

    // bias
    if (tid < 32) ((float4*)(smem + SM_BIAS))[tid] = ((const float4*)bias)[tid];

    // weight tiles: hi and lo, 2048 uint4 each, into pitched smem
    for (int idx = tid; idx < 2048; idx += 256) {
        int r = idx >> 4, c = idx & 15;
        *(uint4*)(smem + SM_WHI + r * (PITCH * 2) + c * 16) = Bimg[idx];
        *(uint4*)(smem + SM_WLO + r * (PITCH * 2) + c * 16) = Bimg[idx + 2048];
    }

    // A tile: fp32 load, split to bf16 hi/lo
    for (int idx = tid; idx < 128 * 32; idx += 256) {
        int row = idx >> 5;
        int k = (idx & 31) * 4;
        int grow = rowBase + row;
        float4 v = (grow < M) ? *(const float4*)&A[grow * 128 + k]
                              : make_float4(0.f, 0.f, 0.f, 0.f);
        __nv_bfloat16 h0 = __float2bfloat16(v.x);
        __nv_bfloat16 h1 = __float2bfloat16(v.y);
        __nv_bfloat16 h2 = __float2bfloat16(v.z);
        __nv_bfloat16 h3 = __float2bfloat16(v.w);
        __nv_bfloat16 l0 = __float2bfloat16(v.x - __bfloat162float(h0));
        __nv_bfloat16 l1 = __float2bfloat16(v.y - __bfloat162float(h1));
        __nv_bfloat16 l2 = __float2bfloat16(v.z - __bfloat162float(h2));
        __nv_bfloat16 l3 = __float2bfloat16(v.w - __bfloat162float(h3));
        __nv_bfloat162 hA = __halves2bfloat162(h0, h1);
        __nv_bfloat162 hB = __halves2bfloat162(h2, h3);
        __nv_bfloat162 lA = __halves2bfloat162(l0, l1);
        __nv_bfloat162 lB = __halves2bfloat162(l2, l3);
        uint2 hp, lp;
        hp.x = *(uint32_t*)&hA; hp.y = *(uint32_t*)&hB;
        lp.x = *(uint32_t*)&lA; lp.y = *(uint32_t*)&lB;
        uint32_t off = (uint32_t)(row * PITCH + k) * 2;
        *(uint2*)(smem + SM_AHI + off) = hp;
        *(uint2*)(smem + SM_ALO + off) = lp;
    }
    __syncthreads();

    // per-lane ldmatrix address pieces: quad decomposition
    int rsub = (lane & 7) + ((lane & 8) ? 8 : 0);   // row within 16
    int csub = (lane & 16) ? 8 : 0;                 // col within 16
    int mrow0 = wid * 16;
    uint32_t aoff = (uint32_t)((mrow0 + rsub) * PITCH + csub) * 2;
    uint32_t ah_base = sb + SM_AHI + aoff;
    uint32_t al_base = sb + SM_ALO + aoff;
    uint32_t woff = (uint32_t)(rsub * PITCH + csub) * 2;
    uint32_t wh_base = sb + SM_WHI + woff;
    uint32_t wl_base = sb + SM_WLO + woff;

    float acc[8][8];
#pragma unroll
    for (int i = 0; i < 8; i++)
#pragma unroll
        for (int j = 0; j < 8; j++) acc[i][j] = 0.f;

#pragma unroll
    for (int kc = 0; kc < 8; kc++) {
        uint32_t ah[4], al[4];
        ldsm_x4(ah, ah_base + kc * 32);
        ldsm_x4(al, al_base + kc * 32);
        uint32_t wrow = (uint32_t)kc * (16 * PITCH * 2);
#pragma unroll
        for (int nb = 0; nb < 8; nb++) {
            uint32_t bh[4], bl[4];
            uint32_t wo = wrow + nb * 32;
            ldsm_x4t(bh, wh_base + wo);
            ldsm_x4t(bl, wl_base + wo);
            mma16816(&acc[nb][0], ah, &bh[0]);
            mma16816(&acc[nb][4], ah, &bh[2]);
            mma16816(&acc[nb][0], ah, &bl[0]);
            mma16816(&acc[nb][4], ah, &bl[2]);
            mma16816(&acc[nb][0], al, &bh[0]);
            mma16816(&acc[nb][4], al, &bh[2]);
        }
    }

    // epilogue: bias + relu + store
    const float* bias_s = (const float*)(smem + SM_BIAS);
    int r0 = rowBase + wid * 16 + (lane >> 2);
    int cq = (lane & 3) * 2;
#pragma unroll
    for (int nb = 0; nb < 8; nb++) {
#pragma unroll
        for (int h = 0; h < 2; h++) {
            int c = nb * 16 + h * 8 + cq;
            float bx = bias_s[c], by = bias_s[c + 1];
            float* base = &acc[nb][h * 4];
            if (r0 < M) {
                float2 v;
                v.x = fmaxf(base[0] + bx, 0.f);
                v.y = fmaxf(base[1] + by, 0.f);
                *(float2*)&C[r0 * 128 + c] = v;
            }
            if (r0 + 8 < M) {
                float2 v;
                v.x = fmaxf(base[2] + bx, 0.f);
                v.y = fmaxf(base[3] + by, 0.f);
                *(float2*)&C[(r0 + 8) * 128 + c] = v;
            }
        }
    }
}

// ---------------- head: out = log_softmax(Y*Wf3 + bf3) ----------------
__global__ __launch_bounds__(256) void k_final(const float* __restrict__ Y,
                                               const float* __restrict__ Wf,
                                               const float* __restrict__ bf,
                                               float* __restrict__ out, int M) {
    __shared__ float Ws[128][16];
    __shared__ float Ys[16][132];
    int t = threadIdx.x;
    int rowBase = blockIdx.x * 16;

    for (int i = t; i < 512; i += 256) {
        float4 v = ((const float4*)Wf)[i];
        int k = i >> 2, c = (i & 3) * 4;
        *(float4*)&Ws[k][c] = v;
    }
    for (int i = t; i < 512; i += 256) {
        int r = i >> 5, c4 = (i & 31) * 4;
        int grow = rowBase + r;
        float4 v = (grow < M) ? ((const float4*)Y)[grow * 32 + (i & 31)]
                              : make_float4(0.f, 0.f, 0.f, 0.f);
        Ys[r][c4 + 0] = v.x; Ys[r][c4 + 1] = v.y;
        Ys[r][c4 + 2] = v.z; Ys[r][c4 + 3] = v.w;
    }
    __syncthreads();

    int r = t >> 4, c = t & 15;
    float acc = __ldg(&bf[c]);
#pragma unroll
    for (int k = 0; k < 128; k++) acc += Ys[r][k] * Ws[k][c];

    float m = acc;
#pragma unroll
    for (int o = 8; o > 0; o >>= 1) m = fmaxf(m, __shfl_xor_sync(0xffffffffu, m, o));
    float e = expf(acc - m);
    float s = e;
#pragma unroll
    for (int o = 8; o > 0; o >>= 1) s += __shfl_xor_sync(0xffffffffu, s, o);
    float res = acc - m - logf(s);

    int grow = rowBase + r;
    if (grow < M) out[grow * 16 + c] = res;
}

// ---------------- launch ----------------
extern "C" void kernel_launch(void* const* d_in, const int* in_sizes, int n_in,
                              void* d_out, int out_size) {
    const float* x   = (const float*)d_in[0];
    const int*   ei  = (const int*)d_in[1];
    const float* W1  = (const float*)d_in[3];
    const float* b1  = (const float*)d_in[4];
    const float* W2  = (const float*)d_in[5];
    const float* b2  = (const float*)d_in[6];
    const float* W3  = (const float*)d_in[7];
    const float* b3  = (const float*)d_in[8];
    const float* Wf1 = (const float*)d_in[9];
    const float* bf1 = (const float*)d_in[10];
    const float* Wf2 = (const float*)d_in[11];
    const float* bf2 = (const float*)d_in[12];
    const float* Wf3 = (const float*)d_in[13];
    const float* bf3 = (const float*)d_in[14];
    float* out = (float*)d_out;

    const int N = N_NODES;
    const int E = N_EDGES;

    float* bufA; float* bufB; __nv_bfloat16* wimg;
    cudaGetSymbolAddress((void**)&bufA, g_bufA);
    cudaGetSymbolAddress((void**)&bufB, g_bufB);
    cudaGetSymbolAddress((void**)&wimg, g_Wimg);

    static int attr_done = 0;
    if (!attr_done) {
        cudaFuncSetAttribute(k_gemm_tc, cudaFuncAttributeMaxDynamicSharedMemorySize, SM_TOTAL);
        attr_done = 1;
    }

    const int NB_SCAN = (N + 1023) / 1024;

    // CSR build
    k_init<<<(N + 255) / 256, 256>>>(N);
    k_count<<<(E + 255) / 256, 256>>>(ei, E);
    k_dinv<<<(N + 255) / 256, 256>>>(N);
    k_scan1<<<NB_SCAN, 1024>>>(N);
    k_scan2<<<1, 32>>>(NB_SCAN, N);
    k_scan3<<<NB_SCAN, 1024>>>(N);
    k_fill<<<(E + 255) / 256, 256>>>(ei, E);

    // weight split images
    k_wconv<<<5, 256>>>(W1, W2, W3, Wf1, Wf2);

    const int spmmBlocks = (N * 32 + 255) / 256;
    const int gemmBlocks = (N + 127) / 128;
    const uint4* img = (const uint4*)wimg;
    const int IMG_STRIDE = 2 * 16384 * 2 / 16;  // uint4s per layer image (4096)

    k_spmm<<<spmmBlocks, 256>>>(x, bufA);
    k_gemm_tc<<<gemmBlocks, 256, SM_TOTAL>>>(bufA, img + 0 * IMG_STRIDE, b1, bufB, N);
    k_spmm<<<spmmBlocks, 256>>>(bufB, bufA);
    k_gemm_tc<<<gemmBlocks, 256, SM_TOTAL>>>(bufA, img + 1 * IMG_STRIDE, b2, bufB, N);
    k_spmm<<<spmmBlocks, 256>>>(bufB, bufA);
    k_gemm_tc<<<gemmBlocks, 256, SM_TOTAL>>>(bufA, img + 2 * IMG_STRIDE, b3, bufB, N);
    k_gemm_tc<<<gemmBlocks, 256, SM_TOTAL>>>(bufB, img + 3 * IMG_STRIDE, bf1, bufA, N);
    k_gemm_tc<<<gemmBlocks, 256, SM_TOTAL>>>(bufA, img + 4 * IMG_STRIDE, bf2, bufB, N);
    k_final<<<(N + 15) / 16, 256>>>(bufB, Wf3, bf3, out, N);
}

// round 4
// speedup vs baseline: 1.2440x; 1.0999x over previous
#include <cuda_runtime.h>
#include <cuda_bf16.h>
#include <math.h>
#include <cstdint>

#define N_NODES 50000
#define N_EDGES 800000
#define F 128
#define NCLS 16

#define PITCH 136                        // bf16 elems per pitched row (272 B)
#define TILE_BYTES (128 * PITCH * 2)     // 34816 B per 128x128 bf16 tile

// ---------------- device scratch ----------------
__device__ float g_bufA[N_NODES * F];
__device__ float g_bufB[N_NODES * F];
__device__ float g_dinv[N_NODES];
__device__ int   g_cnt[N_NODES];
__device__ int   g_cur[N_NODES];
__device__ int   g_rowstart[N_NODES + 1];
__device__ int   g_bsums[64];
__device__ int   g_csr[N_EDGES];
// 5 layers x (hi tile + lo tile), each tile already in the pitched smem layout.
__device__ __align__(16) char g_Wimg[5 * 2 * TILE_BYTES];

// ---------------- CSR construction ----------------
__global__ void k_count(const int* __restrict__ ei, int e) {
    int i = blockIdx.x * blockDim.x + threadIdx.x;
    if (i < e) atomicAdd(&g_cnt[ei[N_EDGES + i]], 1);
}
__global__ void k_scan1(int n) {
    __shared__ int wsum[32];
    int t = threadIdx.x;
    int gid = blockIdx.x * 1024 + t;
    int lane = t & 31, w = t >> 5;
    int v = (gid < n) ? g_cnt[gid] : 0;
    if (gid < n) g_dinv[gid] = rsqrtf((float)(v + 1));   // merged dinv
    int x = v;
#pragma unroll
    for (int o = 1; o < 32; o <<= 1) {
        int y = __shfl_up_sync(0xffffffffu, x, o);
        if (lane >= o) x += y;
    }
    if (lane == 31) wsum[w] = x;
    __syncthreads();
    if (w == 0) {
        int s = wsum[t];
        int xs = s;
#pragma unroll
        for (int o = 1; o < 32; o <<= 1) {
            int y = __shfl_up_sync(0xffffffffu, xs, o);
            if (lane >= o) xs += y;
        }
        wsum[t] = xs - s;
        if (t == 31) g_bsums[blockIdx.x] = xs;
    }
    __syncthreads();
    if (gid < n) g_rowstart[gid] = x - v + wsum[w];
}
__global__ void k_scan2(int nb, int n) {
    if (blockIdx.x == 0 && threadIdx.x == 0) {
        int run = 0;
        for (int i = 0; i < nb; i++) { int v = g_bsums[i]; g_bsums[i] = run; run += v; }
        g_rowstart[n] = run;
    }
}
__global__ void k_scan3(int n) {
    int gid = blockIdx.x * 1024 + threadIdx.x;
    if (gid < n) g_rowstart[gid] += g_bsums[blockIdx.x];
}
__global__ void k_fill(const int* __restrict__ ei, int e) {
    int i = blockIdx.x * blockDim.x + threadIdx.x;
    if (i < e) {
        int d = ei[N_EDGES + i];
        int p = atomicAdd(&g_cur[d], 1);
        g_csr[g_rowstart[d] + p] = ei[i];
    }
}

// ---------------- weight split: W fp32 [k][n] -> pitched hi/lo bf16 tiles ----------------
__global__ void k_wconv(const float* __restrict__ W0, const float* __restrict__ W1,
                        const float* __restrict__ W2, const float* __restrict__ W3,
                        const float* __restrict__ W4) {
    const float* Ws[5] = {W0, W1, W2, W3, W4};
    int b = blockIdx.x;
    const float* W = Ws[b];
    char* hi = &g_Wimg[b * 2 * TILE_BYTES];
    char* lo = hi + TILE_BYTES;
    for (int idx = threadIdx.x; idx < 16384; idx += blockDim.x) {
        int k = idx >> 7, n = idx & 127;
        float v = W[k * 128 + n];
        __nv_bfloat16 h = __float2bfloat16(v);
        __nv_bfloat16 l = __float2bfloat16(v - __bfloat162float(h));
        uint32_t off = (uint32_t)(k * PITCH + n) * 2;
        *(__nv_bfloat16*)(hi + off) = h;
        *(__nv_bfloat16*)(lo + off) = l;
    }
}

// ---------------- SpMM: Z = Â H (warp per row, unroll 4) ----------------
__global__ __launch_bounds__(256) void k_spmm(const float* __restrict__ H,
                                              float* __restrict__ Z) {
    int warp = (blockIdx.x * blockDim.x + threadIdx.x) >> 5;
    if (warp >= N_NODES) return;
    int lane = threadIdx.x & 31;
    const float4* H4 = (const float4*)H;
    float di = g_dinv[warp];
    float4 h = H4[warp * 32 + lane];
    float4 acc;
    acc.x = di * h.x; acc.y = di * h.y; acc.z = di * h.z; acc.w = di * h.w;
    int beg = g_rowstart[warp], end = g_rowstart[warp + 1];
    int j = beg;
    for (; j + 3 < end; j += 4) {
        int s0 = g_csr[j], s1 = g_csr[j + 1], s2 = g_csr[j + 2], s3 = g_csr[j + 3];
        float w0 = g_dinv[s0], w1 = g_dinv[s1], w2 = g_dinv[s2], w3 = g_dinv[s3];
        float4 v0 = H4[s0 * 32 + lane];
        float4 v1 = H4[s1 * 32 + lane];
        float4 v2 = H4[s2 * 32 + lane];
        float4 v3 = H4[s3 * 32 + lane];
        acc.x += w0 * v0.x + w1 * v1.x + w2 * v2.x + w3 * v3.x;
        acc.y += w0 * v0.y + w1 * v1.y + w2 * v2.y + w3 * v3.y;
        acc.z += w0 * v0.z + w1 * v1.z + w2 * v2.z + w3 * v3.z;
        acc.w += w0 * v0.w + w1 * v1.w + w2 * v2.w + w3 * v3.w;
    }
    for (; j < end; j++) {
        int s0 = g_csr[j];
        float w0 = g_dinv[s0];
        float4 v0 = H4[s0 * 32 + lane];
        acc.x += w0 * v0.x; acc.y += w0 * v0.y;
        acc.z += w0 * v0.z; acc.w += w0 * v0.w;
    }
    acc.x *= di; acc.y *= di; acc.z *= di; acc.w *= di;
    ((float4*)Z)[warp * 32 + lane] = acc;
}

// ---------------- mma helpers ----------------
__device__ __forceinline__ void ldsm_x4(uint32_t* r, uint32_t addr) {
    asm volatile("ldmatrix.sync.aligned.m8n8.x4.shared.b16 {%0,%1,%2,%3}, [%4];"
                 : "=r"(r[0]), "=r"(r[1]), "=r"(r[2]), "=r"(r[3]) : "r"(addr));
}
__device__ __forceinline__ void ldsm_x4t(uint32_t* r, uint32_t addr) {
    asm volatile("ldmatrix.sync.aligned.m8n8.x4.trans.shared.b16 {%0,%1,%2,%3}, [%4];"
                 : "=r"(r[0]), "=r"(r[1]), "=r"(r[2]), "=r"(r[3]) : "r"(addr));
}
__device__ __forceinline__ void mma16816(float* d, const uint32_t* a, const uint32_t* b) {
    asm volatile(
        "mma.sync.aligned.m16n8k16.row.col.f32.bf16.bf16.f32 "
        "{%0,%1,%2,%3}, {%4,%5,%6,%7}, {%8,%9}, {%0,%1,%2,%3};"
        : "+f"(d[0]), "+f"(d[1]), "+f"(d[2]), "+f"(d[3])
        : "r"(a[0]), "r"(a[1]), "r"(a[2]), "r"(a[3]), "r"(b[0]), "r"(b[1]));
}
__device__ __forceinline__ uint32_t smem_u32(const void* p) {
    uint32_t a;
    asm("{ .reg .u64 t; cvta.to.shared.u64 t, %1; cvt.u32.u64 %0, t; }" : "=r"(a) : "l"(p));
    return a;
}
__device__ __forceinline__ void cp16(uint32_t saddr, const void* gaddr) {
    asm volatile("cp.async.cg.shared.global [%0], [%1], 16;" :: "r"(saddr), "l"(gaddr));
}

// ---------------- tensor GEMM: C = relu(A*W + b), bf16 hi/lo 3-term split ----------------
#define SM_BIAS 0
#define SM_AHI  1024
#define SM_ALO  (SM_AHI + TILE_BYTES)
#define SM_WHI  (SM_ALO + TILE_BYTES)
#define SM_WLO  (SM_WHI + TILE_BYTES)
#define SM_TOTAL (SM_WLO + TILE_BYTES)   // 140288

__global__ __launch_bounds__(256, 1) void k_gemm_tc(const float* __restrict__ A,
                                                    const char* __restrict__ Wimg,
                                                    const float* __restrict__ bias,
                                                    float* __restrict__ C, int M) {
    extern __shared__ char smem[];
    uint32_t sb = smem_u32(smem);
    int tid = threadIdx.x;
    int wid = tid >> 5, lane = tid & 31;
    int rowBase = blockIdx.x * 128;

    if (tid < 32) ((float4*)(smem + SM_BIAS))[tid] = ((const float4*)bias)[tid];

    // async copy of both pitched weight tiles (hi, lo contiguous: 2*TILE_BYTES)
    {
        const char* src = Wimg;
        for (int i = tid; i < (2 * TILE_BYTES) / 16; i += 256)
            cp16(sb + SM_WHI + i * 16, src + i * 16);
        asm volatile("cp.async.commit_group;");
    }

    // A tile: fp32 load, split to bf16 hi/lo (overlaps with cp.async above)
    for (int idx = tid; idx < 128 * 32; idx += 256) {
        int row = idx >> 5;
        int k = (idx & 31) * 4;
        int grow = rowBase + row;
        float4 v = (grow < M) ? *(const float4*)&A[grow * 128 + k]
                              : make_float4(0.f, 0.f, 0.f, 0.f);
        __nv_bfloat16 h0 = __float2bfloat16(v.x);
        __nv_bfloat16 h1 = __float2bfloat16(v.y);
        __nv_bfloat16 h2 = __float2bfloat16(v.z);
        __nv_bfloat16 h3 = __float2bfloat16(v.w);
        __nv_bfloat16 l0 = __float2bfloat16(v.x - __bfloat162float(h0));
        __nv_bfloat16 l1 = __float2bfloat16(v.y - __bfloat162float(h1));
        __nv_bfloat16 l2 = __float2bfloat16(v.z - __bfloat162float(h2));
        __nv_bfloat16 l3 = __float2bfloat16(v.w - __bfloat162float(h3));
        __nv_bfloat162 hA = __halves2bfloat162(h0, h1);
        __nv_bfloat162 hB = __halves2bfloat162(h2, h3);
        __nv_bfloat162 lA = __halves2bfloat162(l0, l1);
        __nv_bfloat162 lB = __halves2bfloat162(l2, l3);
        uint2 hp, lp;
        hp.x = *(uint32_t*)&hA; hp.y = *(uint32_t*)&hB;
        lp.x = *(uint32_t*)&lA; lp.y = *(uint32_t*)&lB;
        uint32_t off = (uint32_t)(row * PITCH + k) * 2;
        *(uint2*)(smem + SM_AHI + off) = hp;
        *(uint2*)(smem + SM_ALO + off) = lp;
    }
    asm volatile("cp.async.wait_group 0;" ::: "memory");
    __syncthreads();

    // warp grid: 4 warp-rows (m32) x 2 warp-cols (n64)
    int wm = wid >> 1, wn = wid & 1;
    int rsub = (lane & 7) + ((lane & 8) ? 8 : 0);   // 0..15
    int csub = (lane & 16) ? 8 : 0;

    uint32_t a0 = sb + SM_AHI + (uint32_t)((wm * 32 + rsub) * PITCH + csub) * 2;
    uint32_t a1 = sb + SM_AHI + (uint32_t)((wm * 32 + 16 + rsub) * PITCH + csub) * 2;
    uint32_t l0a = a0 + (SM_ALO - SM_AHI);
    uint32_t l1a = a1 + (SM_ALO - SM_AHI);
    uint32_t wbase = sb + SM_WHI + (uint32_t)(rsub * PITCH + wn * 64 + csub) * 2;
    const uint32_t WLO_OFF = TILE_BYTES;
    const uint32_t KROW = 16 * PITCH * 2;

    float acc[2][4][8];
#pragma unroll
    for (int m = 0; m < 2; m++)
#pragma unroll
        for (int g = 0; g < 4; g++)
#pragma unroll
            for (int j = 0; j < 8; j++) acc[m][g][j] = 0.f;

#pragma unroll
    for (int kc = 0; kc < 8; kc++) {
        uint32_t ah[2][4], al[2][4];
        ldsm_x4(ah[0], a0 + kc * 32);
        ldsm_x4(ah[1], a1 + kc * 32);
        ldsm_x4(al[0], l0a + kc * 32);
        ldsm_x4(al[1], l1a + kc * 32);
        uint32_t bh[4][4], bl[4][4];
#pragma unroll
        for (int g = 0; g < 4; g++) ldsm_x4t(bh[g], wbase + kc * KROW + g * 32);
#pragma unroll
        for (int g = 0; g < 4; g++) ldsm_x4t(bl[g], wbase + WLO_OFF + kc * KROW + g * 32);
        // pass 1: hi*hi (16 independent mma)
#pragma unroll
        for (int g = 0; g < 4; g++)
#pragma unroll
            for (int m = 0; m < 2; m++) {
                mma16816(&acc[m][g][0], ah[m], &bh[g][0]);
                mma16816(&acc[m][g][4], ah[m], &bh[g][2]);
            }
        // pass 2: hi*lo
#pragma unroll
        for (int g = 0; g < 4; g++)
#pragma unroll
            for (int m = 0; m < 2; m++) {
                mma16816(&acc[m][g][0], ah[m], &bl[g][0]);
                mma16816(&acc[m][g][4], ah[m], &bl[g][2]);
            }
        // pass 3: lo*hi
#pragma unroll
        for (int g = 0; g < 4; g++)
#pragma unroll
            for (int m = 0; m < 2; m++) {
                mma16816(&acc[m][g][0], al[m], &bh[g][0]);
                mma16816(&acc[m][g][4], al[m], &bh[g][2]);
            }
    }

    // epilogue: bias + relu + store
    const float* bias_s = (const float*)(smem + SM_BIAS);
    int rq = lane >> 2;
    int cq = (lane & 3) * 2;
#pragma unroll
    for (int m = 0; m < 2; m++) {
        int r0 = rowBase + wm * 32 + m * 16 + rq;
#pragma unroll
        for (int g = 0; g < 4; g++) {
#pragma unroll
            for (int h = 0; h < 2; h++) {
                int c = wn * 64 + g * 16 + h * 8 + cq;
                float bx = bias_s[c], by = bias_s[c + 1];
                float* base = &acc[m][g][h * 4];
                if (r0 < M) {
                    float2 v;
                    v.x = fmaxf(base[0] + bx, 0.f);
                    v.y = fmaxf(base[1] + by, 0.f);
                    *(float2*)&C[r0 * 128 + c] = v;
                }
                if (r0 + 8 < M) {
                    float2 v;
                    v.x = fmaxf(base[2] + bx, 0.f);
                    v.y = fmaxf(base[3] + by, 0.f);
                    *(float2*)&C[(r0 + 8) * 128 + c] = v;
                }
            }
        }
    }
}

// ---------------- head: out = log_softmax(Y*Wf3 + bf3) ----------------
__global__ __launch_bounds__(256) void k_final(const float* __restrict__ Y,
                                               const float* __restrict__ Wf,
                                               const float* __restrict__ bf,
                                               float* __restrict__ out, int M) {
    __shared__ float Ws[128][16];
    __shared__ float Ys[16][132];
    int t = threadIdx.x;
    int rowBase = blockIdx.x * 16;

    for (int i = t; i < 512; i += 256) {
        float4 v = ((const float4*)Wf)[i];
        int k = i >> 2, c = (i & 3) * 4;
        *(float4*)&Ws[k][c] = v;
    }
    for (int i = t; i < 512; i += 256) {
        int r = i >> 5, c4 = (i & 31) * 4;
        int grow = rowBase + r;
        float4 v = (grow < M) ? ((const float4*)Y)[grow * 32 + (i & 31)]
                              : make_float4(0.f, 0.f, 0.f, 0.f);
        Ys[r][c4 + 0] = v.x; Ys[r][c4 + 1] = v.y;
        Ys[r][c4 + 2] = v.z; Ys[r][c4 + 3] = v.w;
    }
    __syncthreads();

    int r = t >> 4, c = t & 15;
    float acc = __ldg(&bf[c]);
#pragma unroll
    for (int k = 0; k < 128; k++) acc += Ys[r][k] * Ws[k][c];

    float m = acc;
#pragma unroll
    for (int o = 8; o > 0; o >>= 1) m = fmaxf(m, __shfl_xor_sync(0xffffffffu, m, o));
    float e = expf(acc - m);
    float s = e;
#pragma unroll
    for (int o = 8; o > 0; o >>= 1) s += __shfl_xor_sync(0xffffffffu, s, o);
    float res = acc - m - logf(s);

    int grow = rowBase + r;
    if (grow < M) out[grow * 16 + c] = res;
}

// ---------------- launch ----------------
extern "C" void kernel_launch(void* const* d_in, const int* in_sizes, int n_in,
                              void* d_out, int out_size) {
    const float* x   = (const float*)d_in[0];
    const int*   ei  = (const int*)d_in[1];
    const float* W1  = (const float*)d_in[3];
    const float* b1  = (const float*)d_in[4];
    const float* W2  = (const float*)d_in[5];
    const float* b2  = (const float*)d_in[6];
    const float* W3  = (const float*)d_in[7];
    const float* b3  = (const float*)d_in[8];
    const float* Wf1 = (const float*)d_in[9];
    const float* bf1 = (const float*)d_in[10];
    const float* Wf2 = (const float*)d_in[11];
    const float* bf2 = (const float*)d_in[12];
    const float* Wf3 = (const float*)d_in[13];
    const float* bf3 = (const float*)d_in[14];
    float* out = (float*)d_out;

    const int N = N_NODES;
    const int E = N_EDGES;

    float* bufA; float* bufB; char* wimg; int* cnt; int* cur;
    cudaGetSymbolAddress((void**)&bufA, g_bufA);
    cudaGetSymbolAddress((void**)&bufB, g_bufB);
    cudaGetSymbolAddress((void**)&wimg, g_Wimg);
    cudaGetSymbolAddress((void**)&cnt, g_cnt);
    cudaGetSymbolAddress((void**)&cur, g_cur);

    static int attr_done = 0;
    if (!attr_done) {
        cudaFuncSetAttribute(k_gemm_tc, cudaFuncAttributeMaxDynamicSharedMemorySize, SM_TOTAL);
        attr_done = 1;
    }

    const int NB_SCAN = (N + 1023) / 1024;

    // CSR build
    cudaMemsetAsync(cnt, 0, N * sizeof(int));
    cudaMemsetAsync(cur, 0, N * sizeof(int));
    k_count<<<(E + 255) / 256, 256>>>(ei, E);
    k_scan1<<<NB_SCAN, 1024>>>(N);
    k_scan2<<<1, 32>>>(NB_SCAN, N);
    k_scan3<<<NB_SCAN, 1024>>>(N);
    k_fill<<<(E + 255) / 256, 256>>>(ei, E);

    // weight split images (pitched)
    k_wconv<<<5, 256>>>(W1, W2, W3, Wf1, Wf2);

    const int spmmBlocks = (N * 32 + 255) / 256;
    const int gemmBlocks = (N + 127) / 128;
    const size_t IMG = 2 * (size_t)TILE_BYTES;

    k_spmm<<<spmmBlocks, 256>>>(x, bufA);
    k_gemm_tc<<<gemmBlocks, 256, SM_TOTAL>>>(bufA, wimg + 0 * IMG, b1, bufB, N);
    k_spmm<<<spmmBlocks, 256>>>(bufB, bufA);
    k_gemm_tc<<<gemmBlocks, 256, SM_TOTAL>>>(bufA, wimg + 1 * IMG, b2, bufB, N);
    k_spmm<<<spmmBlocks, 256>>>(bufB, bufA);
    k_gemm_tc<<<gemmBlocks, 256, SM_TOTAL>>>(bufA, wimg + 2 * IMG, b3, bufB, N);
    k_gemm_tc<<<gemmBlocks, 256, SM_TOTAL>>>(bufB, wimg + 3 * IMG, bf1, bufA, N);
    k_gemm_tc<<<gemmBlocks, 256, SM_TOTAL>>>(bufA, wimg + 4 * IMG, bf2, bufB, N);
    k_final<<<(N + 15) / 16, 256>>>(bufB, Wf3, bf3, out, N);
}

// round 6
// speedup vs baseline: 1.4901x; 1.1978x over previous
#include <cuda_runtime.h>
#include <cuda_bf16.h>
#include <math.h>
#include <cstdint>

#define N_NODES 50000
#define N_EDGES 800000
#define F 128
#define NCLS 16

#define PITCH 136                        // bf16 elems per pitched row (272 B)
#define TILE_BYTES (128 * PITCH * 2)     // 34816 B per 128x128 bf16 tile
#define TILES 391                        // ceil(50000/128)
#define GGRID 148                        // persistent GEMM grid

// ---------------- device scratch ----------------
__device__ float g_bufA[N_NODES * F];
__device__ float g_bufB[N_NODES * F];
__device__ float g_dinv[N_NODES];
__device__ __align__(16) int g_cnt[N_NODES];
__device__ __align__(16) int g_cur[N_NODES];
__device__ int   g_rowstart[N_NODES + 1];
__device__ unsigned long long g_tstate[16];
__device__ int   g_csr[N_EDGES];
__device__ __align__(16) char g_Wimg[5 * 2 * TILE_BYTES];

// ---------------- helpers ----------------
__device__ __forceinline__ uint32_t smem_u32(const void* p) {
    uint32_t a;
    asm("{ .reg .u64 t; cvta.to.shared.u64 t, %1; cvt.u32.u64 %0, t; }" : "=r"(a) : "l"(p));
    return a;
}
__device__ __forceinline__ void cp16(uint32_t saddr, const void* gaddr) {
    asm volatile("cp.async.cg.shared.global [%0], [%1], 16;" :: "r"(saddr), "l"(gaddr));
}
__device__ __forceinline__ void cp16z(uint32_t saddr, const void* gaddr, bool valid) {
    int sz = valid ? 16 : 0;
    asm volatile("cp.async.cg.shared.global [%0], [%1], 16, %2;" :: "r"(saddr), "l"(gaddr), "r"(sz));
}
__device__ __forceinline__ void ldsm_x4(uint32_t* r, uint32_t addr) {
    asm volatile("ldmatrix.sync.aligned.m8n8.x4.shared.b16 {%0,%1,%2,%3}, [%4];"
                 : "=r"(r[0]), "=r"(r[1]), "=r"(r[2]), "=r"(r[3]) : "r"(addr));
}
__device__ __forceinline__ void ldsm_x4t(uint32_t* r, uint32_t addr) {
    asm volatile("ldmatrix.sync.aligned.m8n8.x4.trans.shared.b16 {%0,%1,%2,%3}, [%4];"
                 : "=r"(r[0]), "=r"(r[1]), "=r"(r[2]), "=r"(r[3]) : "r"(addr));
}
__device__ __forceinline__ void mma16816(float* d, const uint32_t* a, const uint32_t* b) {
    asm volatile(
        "mma.sync.aligned.m16n8k16.row.col.f32.bf16.bf16.f32 "
        "{%0,%1,%2,%3}, {%4,%5,%6,%7}, {%8,%9}, {%0,%1,%2,%3};"
        : "+f"(d[0]), "+f"(d[1]), "+f"(d[2]), "+f"(d[3])
        : "r"(a[0]), "r"(a[1]), "r"(a[2]), "r"(a[3]), "r"(b[0]), "r"(b[1]));
}

// ---------------- kernel 0: weight split + scratch clear ----------------
__global__ void k_wconv_clear(const float* __restrict__ W0, const float* __restrict__ W1,
                              const float* __restrict__ W2, const float* __restrict__ W3,
                              const float* __restrict__ W4) {
    int b = blockIdx.x;
    int tid = threadIdx.x;
    if (b < 5) {
        const float* Ws[5] = {W0, W1, W2, W3, W4};
        const float* W = Ws[b];
        char* hi = &g_Wimg[b * 2 * TILE_BYTES];
        char* lo = hi + TILE_BYTES;
        for (int idx = tid; idx < 16384; idx += 256) {
            int k = idx >> 7, n = idx & 127;
            float v = W[k * 128 + n];
            __nv_bfloat16 h = __float2bfloat16(v);
            __nv_bfloat16 l = __float2bfloat16(v - __bfloat162float(h));
            uint32_t off = (uint32_t)(k * PITCH + n) * 2;
            *(__nv_bfloat16*)(hi + off) = h;
            *(__nv_bfloat16*)(lo + off) = l;
        }
    } else if (b < 55) {
        int i = (b - 5) * 256 + tid;
        if (i < 12500) ((int4*)g_cnt)[i] = make_int4(0, 0, 0, 0);
    } else if (b < 105) {
        int i = (b - 55) * 256 + tid;
        if (i < 12500) ((int4*)g_cur)[i] = make_int4(0, 0, 0, 0);
    } else {
        if (tid < 16) g_tstate[tid] = 0ULL;
    }
}

// ---------------- kernel 1: degree count ----------------
__global__ void k_count(const int* __restrict__ ei, int e) {
    int i = blockIdx.x * blockDim.x + threadIdx.x;
    if (i < e) atomicAdd(&g_cnt[ei[N_EDGES + i]], 1);
}

// ---------------- kernel 2: single-pass scan (decoupled lookback) + dinv ----------------
__global__ __launch_bounds__(1024) void k_scan(int n, int nb) {
    __shared__ int wsums[32];
    __shared__ int sh_total;
    __shared__ int sh_prefix;
    int tid = threadIdx.x, bid = blockIdx.x;
    int lane = tid & 31, w = tid >> 5;
    int base = bid * 4096 + tid * 4;
    int c0 = 0, c1 = 0, c2 = 0, c3 = 0;
    if (base < n) {  // n % 4 == 0, so base<n implies base+3<n
        int4 v = *(const int4*)&g_cnt[base];
        c0 = v.x; c1 = v.y; c2 = v.z; c3 = v.w;
        g_dinv[base]     = rsqrtf((float)(c0 + 1));
        g_dinv[base + 1] = rsqrtf((float)(c1 + 1));
        g_dinv[base + 2] = rsqrtf((float)(c2 + 1));
        g_dinv[base + 3] = rsqrtf((float)(c3 + 1));
    }
    int s = c0 + c1 + c2 + c3;
    int x = s;
#pragma unroll
    for (int o = 1; o < 32; o <<= 1) {
        int y = __shfl_up_sync(0xffffffffu, x, o);
        if (lane >= o) x += y;
    }
    if (lane == 31) wsums[w] = x;
    __syncthreads();
    if (w == 0) {
        int ws = wsums[lane];
        int xs = ws;
#pragma unroll
        for (int o = 1; o < 32; o <<= 1) {
            int y = __shfl_up_sync(0xffffffffu, xs, o);
            if (lane >= o) xs += y;
        }
        wsums[lane] = xs - ws;
        if (lane == 31) sh_total = xs;
    }
    __syncthreads();
    int excl = x - s + wsums[w];
    int total = sh_total;
    if (tid == 0) {
        int pre = 0;
        if (bid == 0) {
            atomicExch(&g_tstate[0], (2ULL << 32) | (unsigned)total);
        } else {
            atomicExch(&g_tstate[bid], (1ULL << 32) | (unsigned)total);
            int i = bid - 1;
            while (1) {
                unsigned long long v = atomicAdd(&g_tstate[i], 0ULL);
                unsigned f = (unsigned)(v >> 32);
                if (f == 0) continue;
                pre += (int)(unsigned)v;
                if (f == 2) break;
                i--;
            }
            atomicExch(&g_tstate[bid], (2ULL << 32) | (unsigned)(pre + total));
        }
        sh_prefix = pre;
        if (bid == nb - 1) g_rowstart[n] = pre + total;
    }
    __syncthreads();
    int run = sh_prefix + excl;
    if (base < n) {
        g_rowstart[base]     = run;
        g_rowstart[base + 1] = run + c0;
        g_rowstart[base + 2] = run + c0 + c1;
        g_rowstart[base + 3] = run + c0 + c1 + c2;
    }
}

// ---------------- kernel 3: CSR fill ----------------
__global__ void k_fill(const int* __restrict__ ei, int e) {
    int i = blockIdx.x * blockDim.x + threadIdx.x;
    if (i < e) {
        int d = ei[N_EDGES + i];
        int p = atomicAdd(&g_cur[d], 1);
        g_csr[g_rowstart[d] + p] = ei[i];
    }
}

// ---------------- SpMM: Z = Â H (warp per row, unroll 4) ----------------
__global__ __launch_bounds__(256) void k_spmm(const float* __restrict__ H,
                                              float* __restrict__ Z) {
    int warp = (blockIdx.x * blockDim.x + threadIdx.x) >> 5;
    if (warp >= N_NODES) return;
    int lane = threadIdx.x & 31;
    const float4* H4 = (const float4*)H;
    float di = g_dinv[warp];
    float4 h = H4[warp * 32 + lane];
    float4 acc;
    acc.x = di * h.x; acc.y = di * h.y; acc.z = di * h.z; acc.w = di * h.w;
    int beg = g_rowstart[warp], end = g_rowstart[warp + 1];
    int j = beg;
    for (; j + 3 < end; j += 4) {
        int s0 = g_csr[j], s1 = g_csr[j + 1], s2 = g_csr[j + 2], s3 = g_csr[j + 3];
        float w0 = g_dinv[s0], w1 = g_dinv[s1], w2 = g_dinv[s2], w3 = g_dinv[s3];
        float4 v0 = H4[s0 * 32 + lane];
        float4 v1 = H4[s1 * 32 + lane];
        float4 v2 = H4[s2 * 32 + lane];
        float4 v3 = H4[s3 * 32 + lane];
        acc.x += w0 * v0.x + w1 * v1.x + w2 * v2.x + w3 * v3.x;
        acc.y += w0 * v0.y + w1 * v1.y + w2 * v2.y + w3 * v3.y;
        acc.z += w0 * v0.z + w1 * v1.z + w2 * v2.z + w3 * v3.z;
        acc.w += w0 * v0.w + w1 * v1.w + w2 * v2.w + w3 * v3.w;
    }
    for (; j < end; j++) {
        int s0 = g_csr[j];
        float w0 = g_dinv[s0];
        float4 v0 = H4[s0 * 32 + lane];
        acc.x += w0 * v0.x; acc.y += w0 * v0.y;
        acc.z += w0 * v0.z; acc.w += w0 * v0.w;
    }
    acc.x *= di; acc.y *= di; acc.z *= di; acc.w *= di;
    ((float4*)Z)[warp * 32 + lane] = acc;
}

// ---------------- persistent tensor GEMM ----------------
// smem layout
#define SM_BIAS  0
#define SM_WF3   512
#define SM_BF3   (512 + 8192)            // 8704
#define SM_AHI   8768
#define SM_ALO   (SM_AHI + TILE_BYTES)   // 43584
#define SM_WHI   (SM_ALO + TILE_BYTES)   // 78400
#define SM_WLO   (SM_WHI + TILE_BYTES)   // 113216
#define SM_STAGE (SM_WLO + TILE_BYTES)   // 148032
#define SM_TOTAL (SM_STAGE + 65536)      // 213568

template<int MODE>
__global__ __launch_bounds__(256, 1) void k_gemm_tc(
    const float* __restrict__ A, const char* __restrict__ Wimg,
    const float* __restrict__ bias, float* __restrict__ C, int M,
    const float* __restrict__ Wf3, const float* __restrict__ bf3,
    float* __restrict__ out)
{
    extern __shared__ char smem[];
    uint32_t sb = smem_u32(smem);
    int tid = threadIdx.x;
    int wid = tid >> 5, lane = tid & 31;

    if (tid < 32) ((float4*)(smem + SM_BIAS))[tid] = ((const float4*)bias)[tid];
    if (MODE == 1) {
        for (int i = tid; i < 512; i += 256)
            ((float4*)(smem + SM_WF3))[i] = ((const float4*)Wf3)[i];
        if (tid < 16) ((float*)(smem + SM_BF3))[tid] = bf3[tid];
    }

    // W hi/lo tiles (resident for the whole kernel)
    for (int i = tid; i < (2 * TILE_BYTES) / 16; i += 256)
        cp16(sb + SM_WHI + i * 16, Wimg + i * 16);
    asm volatile("cp.async.commit_group;");

    // stage first tile's raw A
    int t = blockIdx.x;
    {
        int rowBase = t * 128;
        for (int i = tid; i < 4096; i += 256) {
            int row = i >> 5, col = i & 31;
            int grow = rowBase + row;
            cp16z(sb + SM_STAGE + i * 16, A + (size_t)grow * 128 + col * 4, grow < M);
        }
    }
    asm volatile("cp.async.commit_group;");

    // constant per-lane addresses
    int wm = wid >> 1, wn = wid & 1;
    int rsub = (lane & 7) + ((lane & 8) ? 8 : 0);
    int csub = (lane & 16) ? 8 : 0;
    uint32_t a0 = sb + SM_AHI + (uint32_t)((wm * 32 + rsub) * PITCH + csub) * 2;
    uint32_t a1 = a0 + (uint32_t)(16 * PITCH * 2);
    uint32_t l0a = a0 + TILE_BYTES;
    uint32_t l1a = a1 + TILE_BYTES;
    uint32_t wbase = sb + SM_WHI + (uint32_t)(rsub * PITCH + wn * 64 + csub) * 2;
    const uint32_t WLO_OFF = TILE_BYTES;
    const uint32_t KROW = 16 * PITCH * 2;

    for (; t < TILES; t += GGRID) {
        int rowBase = t * 128;
        asm volatile("cp.async.wait_group 0;" ::: "memory");
        __syncthreads();

        // convert raw fp32 stage -> bf16 hi/lo pitched tiles
        for (int idx = tid; idx < 4096; idx += 256) {
            int row = idx >> 5;
            int k = (idx & 31) * 4;
            float4 v = *(const float4*)(smem + SM_STAGE + (size_t)(row * 128 + k) * 4);
            __nv_bfloat16 h0 = __float2bfloat16(v.x);
            __nv_bfloat16 h1 = __float2bfloat16(v.y);
            __nv_bfloat16 h2 = __float2bfloat16(v.z);
            __nv_bfloat16 h3 = __float2bfloat16(v.w);
            __nv_bfloat16 l0 = __float2bfloat16(v.x - __bfloat162float(h0));
            __nv_bfloat16 l1 = __float2bfloat16(v.y - __bfloat162float(h1));
            __nv_bfloat16 l2 = __float2bfloat16(v.z - __bfloat162float(h2));
            __nv_bfloat16 l3 = __float2bfloat16(v.w - __bfloat162float(h3));
            __nv_bfloat162 hA = __halves2bfloat162(h0, h1);
            __nv_bfloat162 hB = __halves2bfloat162(h2, h3);
            __nv_bfloat162 lA = __halves2bfloat162(l0, l1);
            __nv_bfloat162 lB = __halves2bfloat162(l2, l3);
            uint2 hp, lp;
            hp.x = *(uint32_t*)&hA; hp.y = *(uint32_t*)&hB;
            lp.x = *(uint32_t*)&lA; lp.y = *(uint32_t*)&lB;
            uint32_t off = (uint32_t)(row * PITCH + k) * 2;
            *(uint2*)(smem + SM_AHI + off) = hp;
            *(uint2*)(smem + SM_ALO + off) = lp;
        }
        __syncthreads();

        // prefetch next tile's raw A (overlaps MMA below)
        int tn = t + GGRID;
        if (tn < TILES) {
            int rb2 = tn * 128;
            for (int i = tid; i < 4096; i += 256) {
                int row = i >> 5, col = i & 31;
                int grow = rb2 + row;
                cp16z(sb + SM_STAGE + i * 16, A + (size_t)grow * 128 + col * 4, grow < M);
            }
        }
        asm volatile("cp.async.commit_group;");

        // MMA: 8 k-chunks x (hi*hi + hi*lo + lo*hi)
        float acc[2][4][8];
#pragma unroll
        for (int m = 0; m < 2; m++)
#pragma unroll
            for (int g = 0; g < 4; g++)
#pragma unroll
                for (int j = 0; j < 8; j++) acc[m][g][j] = 0.f;

#pragma unroll
        for (int kc = 0; kc < 8; kc++) {
            uint32_t ah[2][4], al[2][4];
            ldsm_x4(ah[0], a0 + kc * 32);
            ldsm_x4(ah[1], a1 + kc * 32);
            ldsm_x4(al[0], l0a + kc * 32);
            ldsm_x4(al[1], l1a + kc * 32);
            uint32_t bh[4][4], bl[4][4];
#pragma unroll
            for (int g = 0; g < 4; g++) ldsm_x4t(bh[g], wbase + kc * KROW + g * 32);
#pragma unroll
            for (int g = 0; g < 4; g++) ldsm_x4t(bl[g], wbase + WLO_OFF + kc * KROW + g * 32);
#pragma unroll
            for (int g = 0; g < 4; g++)
#pragma unroll
                for (int m = 0; m < 2; m++) {
                    mma16816(&acc[m][g][0], ah[m], &bh[g][0]);
                    mma16816(&acc[m][g][4], ah[m], &bh[g][2]);
                }
#pragma unroll
            for (int g = 0; g < 4; g++)
#pragma unroll
                for (int m = 0; m < 2; m++) {
                    mma16816(&acc[m][g][0], ah[m], &bl[g][0]);
                    mma16816(&acc[m][g][4], ah[m], &bl[g][2]);
                }
#pragma unroll
            for (int g = 0; g < 4; g++)
#pragma unroll
                for (int m = 0; m < 2; m++) {
                    mma16816(&acc[m][g][0], al[m], &bh[g][0]);
                    mma16816(&acc[m][g][4], al[m], &bh[g][2]);
                }
        }

        const float* bias_s = (const float*)(smem + SM_BIAS);
        int rq = lane >> 2;
        int cq = (lane & 3) * 2;

        if (MODE == 0) {
            // epilogue: bias + relu -> gmem
#pragma unroll
            for (int m = 0; m < 2; m++) {
                int r0 = rowBase + wm * 32 + m * 16 + rq;
#pragma unroll
                for (int g = 0; g < 4; g++) {
#pragma unroll
                    for (int h = 0; h < 2; h++) {
                        int c = wn * 64 + g * 16 + h * 8 + cq;
                        float bx = bias_s[c], by = bias_s[c + 1];
                        float* base = &acc[m][g][h * 4];
                        if (r0 < M) {
                            float2 v;
                            v.x = fmaxf(base[0] + bx, 0.f);
                            v.y = fmaxf(base[1] + by, 0.f);
                            *(float2*)&C[(size_t)r0 * 128 + c] = v;
                        }
                        if (r0 + 8 < M) {
                            float2 v;
                            v.x = fmaxf(base[2] + bx, 0.f);
                            v.y = fmaxf(base[3] + by, 0.f);
                            *(float2*)&C[(size_t)(r0 + 8) * 128 + c] = v;
                        }
                    }
                }
            }
        } else {
            // FIX: all warps must finish their ldsm reads of the A hi/lo tiles
            // before any warp overwrites that smem region with Ys.
            __syncthreads();
            // epilogue: bias + relu -> smem Y, then fused head + log_softmax
            float* Ys = (float*)(smem + SM_AHI);
#pragma unroll
            for (int m = 0; m < 2; m++) {
                int rl = wm * 32 + m * 16 + rq;
#pragma unroll
                for (int g = 0; g < 4; g++) {
#pragma unroll
                    for (int h = 0; h < 2; h++) {
                        int c = wn * 64 + g * 16 + h * 8 + cq;
                        float bx = bias_s[c], by = bias_s[c + 1];
                        float* base = &acc[m][g][h * 4];
                        float2 v;
                        v.x = fmaxf(base[0] + bx, 0.f);
                        v.y = fmaxf(base[1] + by, 0.f);
                        *(float2*)&Ys[rl * 128 + c] = v;
                        float2 v2;
                        v2.x = fmaxf(base[2] + bx, 0.f);
                        v2.y = fmaxf(base[3] + by, 0.f);
                        *(float2*)&Ys[(rl + 8) * 128 + c] = v2;
                    }
                }
            }
            __syncthreads();

            const float* Wfs = (const float*)(smem + SM_WF3);
            const float* bfs = (const float*)(smem + SM_BF3);
            int hr = tid >> 4, hc = tid & 15;
#pragma unroll
            for (int p = 0; p < 8; p++) {
                int r = p * 16 + hr;
                float a2 = bfs[hc];
#pragma unroll 16
                for (int k = 0; k < 128; k++) a2 += Ys[r * 128 + k] * Wfs[k * 16 + hc];
                float mx = a2;
#pragma unroll
                for (int o = 8; o > 0; o >>= 1) mx = fmaxf(mx, __shfl_xor_sync(0xffffffffu, mx, o));
                float e = expf(a2 - mx);
                float ssum = e;
#pragma unroll
                for (int o = 8; o > 0; o >>= 1) ssum += __shfl_xor_sync(0xffffffffu, ssum, o);
                float res = a2 - mx - logf(ssum);
                int grow = rowBase + r;
                if (grow < M) out[(size_t)grow * 16 + hc] = res;
            }
            // loop-top __syncthreads protects Ys vs next tile's convert
        }
    }
}

// ---------------- launch ----------------
extern "C" void kernel_launch(void* const* d_in, const int* in_sizes, int n_in,
                              void* d_out, int out_size) {
    const float* x   = (const float*)d_in[0];
    const int*   ei  = (const int*)d_in[1];
    const float* W1  = (const float*)d_in[3];
    const float* b1  = (const float*)d_in[4];
    const float* W2  = (const float*)d_in[5];
    const float* b2  = (const float*)d_in[6];
    const float* W3  = (const float*)d_in[7];
    const float* b3  = (const float*)d_in[8];
    const float* Wf1 = (const float*)d_in[9];
    const float* bf1 = (const float*)d_in[10];
    const float* Wf2 = (const float*)d_in[11];
    const float* bf2 = (const float*)d_in[12];
    const float* Wf3 = (const float*)d_in[13];
    const float* bf3 = (const float*)d_in[14];
    float* out = (float*)d_out;

    const int N = N_NODES;
    const int E = N_EDGES;

    float* bufA; float* bufB; char* wimg;
    cudaGetSymbolAddress((void**)&bufA, g_bufA);
    cudaGetSymbolAddress((void**)&bufB, g_bufB);
    cudaGetSymbolAddress((void**)&wimg, g_Wimg);

    static int attr_done = 0;
    if (!attr_done) {
        cudaFuncSetAttribute(k_gemm_tc<0>, cudaFuncAttributeMaxDynamicSharedMemorySize, SM_TOTAL);
        cudaFuncSetAttribute(k_gemm_tc<1>, cudaFuncAttributeMaxDynamicSharedMemorySize, SM_TOTAL);
        attr_done = 1;
    }

    // launch order chosen so ncu (-s 5) captures the first GEMM
    k_wconv_clear<<<106, 256>>>(W1, W2, W3, Wf1, Wf2);            // 0
    k_count<<<(E + 255) / 256, 256>>>(ei, E);                     // 1
    k_scan<<<13, 1024>>>(N, 13);                                  // 2
    k_fill<<<(E + 255) / 256, 256>>>(ei, E);                      // 3

    const int spmmBlocks = (N * 32 + 255) / 256;
    const size_t IMG = 2 * (size_t)TILE_BYTES;

    k_spmm<<<spmmBlocks, 256>>>(x, bufA);                         // 4
    k_gemm_tc<0><<<GGRID, 256, SM_TOTAL>>>(bufA, wimg + 0 * IMG, b1, bufB, N,
                                           nullptr, nullptr, nullptr);   // 5 <- ncu
    k_spmm<<<spmmBlocks, 256>>>(bufB, bufA);
    k_gemm_tc<0><<<GGRID, 256, SM_TOTAL>>>(bufA, wimg + 1 * IMG, b2, bufB, N,
                                           nullptr, nullptr, nullptr);
    k_spmm<<<spmmBlocks, 256>>>(bufB, bufA);
    k_gemm_tc<0><<<GGRID, 256, SM_TOTAL>>>(bufA, wimg + 2 * IMG, b3, bufB, N,
                                           nullptr, nullptr, nullptr);
    k_gemm_tc<0><<<GGRID, 256, SM_TOTAL>>>(bufB, wimg + 3 * IMG, bf1, bufA, N,
                                           nullptr, nullptr, nullptr);
    k_gemm_tc<1><<<GGRID, 256, SM_TOTAL>>>(bufA, wimg + 4 * IMG, bf2, bufB, N,
                                           Wf3, bf3, out);
}